// round 17
// baseline (speedup 1.0000x reference)
#include <cuda_runtime.h>
#include <cstdint>

// QuantumConv1d — single-kernel producer/consumer.
//  Blocks 0..767: producers. Per (tile,b): warp0 folds the circuit into 4
//    quadratic forms (lane-distributed, ~40 regs) while warps 1-15 stage the x
//    tile; quad-split conv + shfl reduce -> g_ez (coalesced scalar stores);
//    __threadfence + flag release.
//  Blocks 768..3839: writers. Each handles 128 o x 128 l; one thread spins on
//    the tile flag (__nanosleep), then the R13-proven float4 __stcs store loop.
//  Writers of early tiles overlap later producers; worst case degenerates to
//  the serial split. Flags zeroed via cudaMemsetAsync each call.

#define C_IN     80
#define L_IN     3000
#define OUT_CH   512
#define KW       3
#define TILE_L   128
#define THREADS  512
#define B_MAX    32
#define N_TILES  24                        // ceil(3000/128)
#define NP       (N_TILES * B_MAX)         // 768 producers
#define WPT      4                         // writer CTAs per tile (128 o each)
#define NWRT     (NP * WPT)                // 3072 writers

__device__ float g_ez[B_MAX * L_IN * 4];   // expz per (b,l,q)
__device__ int   g_flag[NP];

__global__ __launch_bounds__(THREADS, 3)
void qconv_pc(const float* __restrict__ x,
              const float* __restrict__ W_pre,
              const float* __restrict__ b_pre,
              const float* __restrict__ W_post,
              const float* __restrict__ b_post,
              const float* __restrict__ qw,
              float* __restrict__ out)
{
    __shared__ float x_s[C_IN][130];        // j=0 <-> l0-1 .. j=129 <-> l0+128
    __shared__ float w_s[C_IN * 12];        // [c][k][q]
    __shared__ float Q_s[4][16];
    __shared__ float bpre_s[4];

    const int tid = threadIdx.x;
    const int blk = blockIdx.x;

    if (blk < NP) {
        // ===================== PRODUCER =====================
        const int p    = blk;
        const int tile = p % N_TILES;
        const int b    = p / N_TILES;
        const int l0   = tile * TILE_L;
        const float* xb = x + (size_t)b * C_IN * L_IN;

        // -------- Phase 0: Q fold (warp 0, lane-distributed) || staging --------
        if (tid < 32) {
            const int lane = tid;
            const int jm   = lane >> 2;
            const int k    = lane & 3;
            float ar0 = (jm == k) ? 1.f : 0.f, ai0 = 0.f;
            float ar1 = 0.f,                   ai1 = 0.f;

            {   // wire 0 (s=8): in-lane pair
                float phi = __ldg(qw + 0), th = __ldg(qw + 1), om = __ldg(qw + 2);
                float sh, ch; __sincosf(0.5f * th, &sh, &ch);
                float a = 0.5f * (phi + om), d = 0.5f * (phi - om);
                float sa, ca, sd, cd;
                __sincosf(a, &sa, &ca); __sincosf(d, &sd, &cd);
                float u00r =  ch * ca, u00i = -ch * sa;
                float u01r = -sh * cd, u01i = -sh * sd;
                float u10r =  sh * cd, u10i = -sh * sd;
                float u11r =  ch * ca, u11i =  ch * sa;
                float n0r = u00r*ar0 - u00i*ai0 + u01r*ar1 - u01i*ai1;
                float n0i = u00r*ai0 + u00i*ar0 + u01r*ai1 + u01i*ar1;
                float n1r = u10r*ar0 - u10i*ai0 + u11r*ar1 - u11i*ai1;
                float n1i = u10r*ai0 + u10i*ar0 + u11r*ai1 + u11i*ar1;
                ar0 = n0r; ai0 = n0i; ar1 = n1r; ai1 = n1i;
            }
            #pragma unroll
            for (int w = 1; w < 4; w++) {   // wires 1..3: partner lane = lane ^ 4s
                float phi = __ldg(qw + w * 3 + 0), th = __ldg(qw + w * 3 + 1), om = __ldg(qw + w * 3 + 2);
                float sh, ch; __sincosf(0.5f * th, &sh, &ch);
                float a = 0.5f * (phi + om), d = 0.5f * (phi - om);
                float sa, ca, sd, cd;
                __sincosf(a, &sa, &ca); __sincosf(d, &sd, &cd);
                float u00r =  ch * ca, u00i = -ch * sa;
                float u01r = -sh * cd, u01i = -sh * sd;
                float u10r =  sh * cd, u10i = -sh * sd;
                float u11r =  ch * ca, u11i =  ch * sa;
                const int s = 8 >> w;
                float p0r = __shfl_xor_sync(0xffffffffu, ar0, 4 * s);
                float p0i = __shfl_xor_sync(0xffffffffu, ai0, 4 * s);
                float p1r = __shfl_xor_sync(0xffffffffu, ar1, 4 * s);
                float p1i = __shfl_xor_sync(0xffffffffu, ai1, 4 * s);
                float n0r, n0i, n1r, n1i;
                if ((jm & s) == 0) {
                    n0r = u00r*ar0 - u00i*ai0 + u01r*p0r - u01i*p0i;
                    n0i = u00r*ai0 + u00i*ar0 + u01r*p0i + u01i*p0r;
                    n1r = u00r*ar1 - u00i*ai1 + u01r*p1r - u01i*p1i;
                    n1i = u00r*ai1 + u00i*ar1 + u01r*p1i + u01i*p1r;
                } else {
                    n0r = u10r*p0r - u10i*p0i + u11r*ar0 - u11i*ai0;
                    n0i = u10r*p0i + u10i*p0r + u11r*ai0 + u11i*ar0;
                    n1r = u10r*p1r - u10i*p1i + u11r*ar1 - u11i*ai1;
                    n1i = u10r*p1i + u10i*p1r + u11r*ai1 + u11i*ar1;
                }
                ar0 = n0r; ai0 = n0i; ar1 = n1r; ai1 = n1i;
            }
            // CNOT chain folded into index remap
            int f0 = jm;
            if (f0 & 4) f0 ^= 2;
            if (f0 & 2) f0 ^= 1;
            int f1 = (jm + 8) ^ 4;
            if (f1 & 4) f1 ^= 2;
            if (f1 & 2) f1 ^= 1;

            float Qa[4][4];
            #pragma unroll
            for (int m = 0; m < 4; m++) {
                const int src = (lane & ~3) | m;
                float a0rm = __shfl_sync(0xffffffffu, ar0, src);
                float a0im = __shfl_sync(0xffffffffu, ai0, src);
                float a1rm = __shfl_sync(0xffffffffu, ar1, src);
                float a1im = __shfl_sync(0xffffffffu, ai1, src);
                float p0 = ar0 * a0rm + ai0 * a0im;
                float p1 = ar1 * a1rm + ai1 * a1im;
                Qa[0][m] = ((f0 & 8) ? -p0 : p0) + ((f1 & 8) ? -p1 : p1);
                Qa[1][m] = ((f0 & 4) ? -p0 : p0) + ((f1 & 4) ? -p1 : p1);
                Qa[2][m] = ((f0 & 2) ? -p0 : p0) + ((f1 & 2) ? -p1 : p1);
                Qa[3][m] = ((f0 & 1) ? -p0 : p0) + ((f1 & 1) ? -p1 : p1);
            }
            #pragma unroll
            for (int q = 0; q < 4; q++)
                #pragma unroll
                for (int m = 0; m < 4; m++) {
                    float v = Qa[q][m];
                    v += __shfl_xor_sync(0xffffffffu, v, 4);
                    v += __shfl_xor_sync(0xffffffffu, v, 8);
                    v += __shfl_xor_sync(0xffffffffu, v, 16);
                    Qa[q][m] = v;
                }
            if (lane < 4) {
                #pragma unroll
                for (int q = 0; q < 4; q++)
                    #pragma unroll
                    for (int m = 0; m < 4; m++)
                        Q_s[q][lane * 4 + m] = Qa[q][m];
                bpre_s[lane] = b_pre[lane];
            }
        } else {
            const int t = tid - 32;                     // 0..479
            for (int i = t; i < C_IN * 12; i += THREADS - 32) {
                int c = i / 12; int r = i - c * 12; int k = r >> 2; int q = r & 3;
                w_s[i] = W_pre[q * (C_IN * KW) + c * KW + k];
            }
            // interior j = 1..128 <-> l = l0..l0+127 (aligned float4 reads)
            for (int i = t; i < C_IN * 32; i += THREADS - 32) {
                int c  = i >> 5;
                int qq = i & 31;
                int l  = l0 + qq * 4;
                float4 vv;
                if (l + 3 < L_IN) {
                    vv = *(const float4*)(xb + (size_t)c * L_IN + l);
                } else {
                    vv.x = (l + 0 < L_IN) ? xb[(size_t)c * L_IN + l + 0] : 0.f;
                    vv.y = (l + 1 < L_IN) ? xb[(size_t)c * L_IN + l + 1] : 0.f;
                    vv.z = (l + 2 < L_IN) ? xb[(size_t)c * L_IN + l + 2] : 0.f;
                    vv.w = (l + 3 < L_IN) ? xb[(size_t)c * L_IN + l + 3] : 0.f;
                }
                x_s[c][1 + qq * 4] = vv.x;
                x_s[c][2 + qq * 4] = vv.y;
                x_s[c][3 + qq * 4] = vv.z;
                x_s[c][4 + qq * 4] = vv.w;
            }
            for (int c = t; c < C_IN; c += THREADS - 32) {
                int ll = l0 - 1;
                x_s[c][0]   = (ll >= 0) ? xb[(size_t)c * L_IN + ll] : 0.f;
                int lr = l0 + TILE_L;
                x_s[c][129] = (lr < L_IN) ? xb[(size_t)c * L_IN + lr] : 0.f;
            }
        }
        __syncthreads();

        // -------- Phase 1: quad-split conv + shfl reduce + one quadratic form ----
        {
            const int pos = tid >> 2;                   // 0..127
            const int grp = tid & 3;                    // 0..3
            const int c0  = grp * 20;

            float v0 = 0.f, v1 = 0.f, v2 = 0.f, v3 = 0.f;
            #pragma unroll
            for (int ci = 0; ci < 20; ci++) {
                const int c = c0 + ci;
                float xa  = x_s[c][pos];
                float xb1 = x_s[c][pos + 1];
                float xc  = x_s[c][pos + 2];
                const float4* wr = (const float4*)&w_s[c * 12];
                float4 w0 = wr[0], w1 = wr[1], w2 = wr[2];
                v0 += w0.x * xa + w1.x * xb1 + w2.x * xc;
                v1 += w0.y * xa + w1.y * xb1 + w2.y * xc;
                v2 += w0.z * xa + w1.z * xb1 + w2.z * xc;
                v3 += w0.w * xa + w1.w * xb1 + w2.w * xc;
            }
            v0 += __shfl_xor_sync(0xffffffffu, v0, 1);
            v1 += __shfl_xor_sync(0xffffffffu, v1, 1);
            v2 += __shfl_xor_sync(0xffffffffu, v2, 1);
            v3 += __shfl_xor_sync(0xffffffffu, v3, 1);
            v0 += __shfl_xor_sync(0xffffffffu, v0, 2);
            v1 += __shfl_xor_sync(0xffffffffu, v1, 2);
            v2 += __shfl_xor_sync(0xffffffffu, v2, 2);
            v3 += __shfl_xor_sync(0xffffffffu, v3, 2);

            v0 += bpre_s[0]; v1 += bpre_s[1]; v2 += bpre_s[2]; v3 += bpre_s[3];

            const int l = l0 + pos;
            if (l < L_IN) {
                const float inv = __frcp_rn(v0 * v0 + v1 * v1 + v2 * v2 + v3 * v3);
                const float* Qr = &Q_s[grp][0];
                float s;
                s  = v0 * (Qr[0]  * v0 + Qr[1]  * v1 + Qr[2]  * v2 + Qr[3]  * v3);
                s += v1 * (Qr[4]  * v0 + Qr[5]  * v1 + Qr[6]  * v2 + Qr[7]  * v3);
                s += v2 * (Qr[8]  * v0 + Qr[9]  * v1 + Qr[10] * v2 + Qr[11] * v3);
                s += v3 * (Qr[12] * v0 + Qr[13] * v1 + Qr[14] * v2 + Qr[15] * v3);
                g_ez[((size_t)b * L_IN + l) * 4 + grp] = s * inv;   // coalesced
            }
        }
        __syncthreads();
        if (tid == 0) {
            __threadfence();                    // release g_ez before flag
            atomicExch(&g_flag[p], 1);
        }
    } else {
        // ===================== WRITER =====================
        const int w    = blk - NP;
        const int p    = w >> 2;                // producer index (tile,b)
        const int oc   = w & 3;                 // o-chunk 0..3 (128 o each)
        const int tile = p % N_TILES;
        const int b    = p / N_TILES;
        const int l0   = tile * TILE_L;

        if (tid == 0) {
            while (atomicAdd(&g_flag[p], 0) == 0) __nanosleep(64);
            __threadfence();                    // acquire
        }
        __syncthreads();

        const int lane = tid & 31;
        const int wrp  = tid >> 5;              // 0..15
        const int l4   = l0 + lane * 4;
        if (l4 >= L_IN) return;                 // after the sync: safe

        const float4* ezp = (const float4*)g_ez + ((size_t)b * L_IN + l4);
        const float4 e0 = __ldg(ezp + 0);
        const float4 e1 = __ldg(ezp + 1);
        const float4 e2 = __ldg(ezp + 2);
        const float4 e3 = __ldg(ezp + 3);

        float* outb = out + (size_t)b * OUT_CH * L_IN;
        const int o0 = oc * 128;

        #pragma unroll 8
        for (int it = 0; it < 8; it++) {
            const int o = o0 + it * 16 + wrp;
            const float4 wp = __ldg((const float4*)(W_post + o * 4));
            const float  bp = __ldg(b_post + o);
            float4 r;
            r.x = fmaf(wp.x, e0.x, fmaf(wp.y, e0.y, fmaf(wp.z, e0.z, fmaf(wp.w, e0.w, bp))));
            r.y = fmaf(wp.x, e1.x, fmaf(wp.y, e1.y, fmaf(wp.z, e1.z, fmaf(wp.w, e1.w, bp))));
            r.z = fmaf(wp.x, e2.x, fmaf(wp.y, e2.y, fmaf(wp.z, e2.z, fmaf(wp.w, e2.w, bp))));
            r.w = fmaf(wp.x, e3.x, fmaf(wp.y, e3.y, fmaf(wp.z, e3.z, fmaf(wp.w, e3.w, bp))));
            __stcs((float4*)(outb + (size_t)o * L_IN + l4), r);
        }
    }
}

extern "C" void kernel_launch(void* const* d_in, const int* in_sizes, int n_in,
                              void* d_out, int out_size)
{
    const float* x      = (const float*)d_in[0];
    const float* W_pre  = (const float*)d_in[1];
    const float* b_pre  = (const float*)d_in[2];
    const float* W_post = (const float*)d_in[3];
    const float* b_post = (const float*)d_in[4];
    const float* qw     = (const float*)d_in[5];
    float* out = (float*)d_out;

    static void* flag_ptr = nullptr;
    if (!flag_ptr) cudaGetSymbolAddress(&flag_ptr, g_flag);

    cudaMemsetAsync(flag_ptr, 0, NP * sizeof(int), 0);   // reset flags (graph-capturable)
    qconv_pc<<<NP + NWRT, THREADS>>>(x, W_pre, b_pre, W_post, b_post, qw, out);
}